// round 3
// baseline (speedup 1.0000x reference)
#include <cuda_runtime.h>
#include <math.h>

#define N_NODES   100000
#define N_EDGES   1600000
#define N_GRAPHS  1024
#define HDIM      64
#define EPSV      1e-7f
#define LOG2E     1.4426950408889634f
#define SHL2      57.707801635558536f   /* 40 * log2(e) */
#define SCAN_BLK  512
#define NSCAN     ((N_NODES + SCAN_BLK - 1) / SCAN_BLK)   // 196

typedef unsigned long long ull;

// ---------------- scratch (static device globals; no allocation) -------------
__device__ float g_h0[N_NODES * HDIM];
__device__ float g_h1[N_NODES * HDIM];
__device__ float g_pool[N_GRAPHS * HDIM];
__device__ float g_cnt[N_GRAPHS];
// CSR
__device__ int   g_deg[N_NODES];
__device__ int   g_off[N_NODES];
__device__ int   g_cursor[N_NODES];
__device__ int   g_bsum[NSCAN];
__device__ int   g_src_s[N_EDGES];
__device__ float g_ea_s[(size_t)N_EDGES * 8];

__device__ __forceinline__ void red4(float* p, float a, float b, float c, float d) {
    asm volatile("red.global.add.v4.f32 [%0], {%1,%2,%3,%4};"
                 :: "l"(p), "f"(a), "f"(b), "f"(c), "f"(d) : "memory");
}
__device__ __forceinline__ ull pack2(float x, float y) {
    ull r; asm("mov.b64 %0, {%1, %2};" : "=l"(r) : "f"(x), "f"(y)); return r;
}
__device__ __forceinline__ void unpack2(float& x, float& y, ull v) {
    asm("mov.b64 {%0, %1}, %2;" : "=f"(x), "=f"(y) : "l"(v));
}
__device__ __forceinline__ void fma2(ull& d, ull a, ull b) {
    asm("fma.rn.f32x2 %0, %1, %2, %0;" : "+l"(d) : "l"(a), "l"(b));
}

// ---------------- zero small scratch ------------------------------------------
__global__ void __launch_bounds__(256) zero_small() {
    int i = blockIdx.x * 256 + threadIdx.x;
    if (i < N_NODES) g_deg[i] = 0;
    if (i < N_GRAPHS * HDIM) g_pool[i] = 0.0f;
    if (i < N_GRAPHS) g_cnt[i] = 0.0f;
}

// ---------------- h0 = x @ node_W + node_b  (16 -> 64) ------------------------
__global__ void __launch_bounds__(256) input_proj(const float* __restrict__ x,
                                                  const float* __restrict__ W,
                                                  const float* __restrict__ b) {
    __shared__ float4 sW[256];
    __shared__ float4 sb[16];
    int tid = threadIdx.x;
    sW[tid] = ((const float4*)W)[tid];
    if (tid < 16) sb[tid] = ((const float4*)b)[tid];
    __syncthreads();

    int t = blockIdx.x * 256 + tid;
    int n = t >> 4, g = t & 15;
    if (n >= N_NODES) return;
    const float4* xr = (const float4*)(x + n * 16);
    float4 x0 = xr[0], x1 = xr[1], x2 = xr[2], x3 = xr[3];
    float4 acc = sb[g];
#define ISTEP(av, kk) { float4 w = sW[(kk)*16 + g]; \
    acc.x = fmaf(av, w.x, acc.x); acc.y = fmaf(av, w.y, acc.y); \
    acc.z = fmaf(av, w.z, acc.z); acc.w = fmaf(av, w.w, acc.w); }
    ISTEP(x0.x, 0)  ISTEP(x0.y, 1)  ISTEP(x0.z, 2)  ISTEP(x0.w, 3)
    ISTEP(x1.x, 4)  ISTEP(x1.y, 5)  ISTEP(x1.z, 6)  ISTEP(x1.w, 7)
    ISTEP(x2.x, 8)  ISTEP(x2.y, 9)  ISTEP(x2.z, 10) ISTEP(x2.w, 11)
    ISTEP(x3.x, 12) ISTEP(x3.y, 13) ISTEP(x3.z, 14) ISTEP(x3.w, 15)
#undef ISTEP
    ((float4*)(g_h0 + (size_t)n * HDIM))[g] = acc;
}

// ---------------- CSR build: histogram, scan, scatter --------------------------
__global__ void __launch_bounds__(256) hist_kernel(const int* __restrict__ edst) {
    int e = blockIdx.x * 256 + threadIdx.x;
    if (e < N_EDGES) atomicAdd(&g_deg[edst[e]], 1);
}

__global__ void __launch_bounds__(SCAN_BLK) scan1_kernel() {
    __shared__ int wsum[SCAN_BLK / 32];
    int d = blockIdx.x * SCAN_BLK + threadIdx.x;
    int v = (d < N_NODES) ? g_deg[d] : 0;
    int lane = threadIdx.x & 31, w = threadIdx.x >> 5;
    int inc = v;
#pragma unroll
    for (int o = 1; o < 32; o <<= 1) {
        int t = __shfl_up_sync(0xffffffffu, inc, o);
        if (lane >= o) inc += t;
    }
    if (lane == 31) wsum[w] = inc;
    __syncthreads();
    if (w == 0) {
        int s = (lane < SCAN_BLK / 32) ? wsum[lane] : 0;
#pragma unroll
        for (int o = 1; o < 16; o <<= 1) {
            int t = __shfl_up_sync(0xffffffffu, s, o);
            if (lane >= o) s += t;
        }
        if (lane < SCAN_BLK / 32) wsum[lane] = s;
    }
    __syncthreads();
    int base = (w > 0) ? wsum[w - 1] : 0;
    if (d < N_NODES) g_off[d] = base + inc - v;
    if (threadIdx.x == SCAN_BLK - 1) g_bsum[blockIdx.x] = base + inc;
}

__global__ void __launch_bounds__(256) scan2_kernel() {
    __shared__ int wsum[8];
    int i = threadIdx.x;
    int v = (i < NSCAN) ? g_bsum[i] : 0;
    int lane = i & 31, w = i >> 5;
    int inc = v;
#pragma unroll
    for (int o = 1; o < 32; o <<= 1) {
        int t = __shfl_up_sync(0xffffffffu, inc, o);
        if (lane >= o) inc += t;
    }
    if (lane == 31) wsum[w] = inc;
    __syncthreads();
    if (w == 0 && lane < 8) {
        int s = wsum[lane];
#pragma unroll
        for (int o = 1; o < 8; o <<= 1) {
            int t = __shfl_up_sync(0x000000ffu, s, o);
            if (lane >= o) s += t;
        }
        wsum[lane] = s;
    }
    __syncthreads();
    int base = (w > 0) ? wsum[w - 1] : 0;
    if (i < NSCAN) g_bsum[i] = base + inc - v;
}

__global__ void __launch_bounds__(256) scan3_kernel(const int* __restrict__ batch) {
    int d = blockIdx.x * 256 + threadIdx.x;
    if (d < N_NODES) {
        int o = g_off[d] + g_bsum[d / SCAN_BLK];
        g_off[d] = o;
        g_cursor[d] = o;
        atomicAdd(&g_cnt[batch[d]], 1.0f);   // per-graph node counts (once)
    }
}

__global__ void __launch_bounds__(256) scatter_kernel(const float* __restrict__ edge_attr,
                                                      const int* __restrict__ esrc,
                                                      const int* __restrict__ edst) {
    int e = blockIdx.x * 256 + threadIdx.x;
    if (e >= N_EDGES) return;
    int d = edst[e];
    int pos = atomicAdd(&g_cursor[d], 1);
    const float4* a = (const float4*)(edge_attr + (size_t)e * 8);
    float4 a0 = __ldg(a), a1 = __ldg(a + 1);
    g_src_s[pos] = esrc[e];
    float4* o = (float4*)(g_ea_s + (size_t)pos * 8);
    o[0] = a0; o[1] = a1;
}

// ---------------- fused conv: per-dst softmax-agg + root add + MLP (+pool) -----
// 64 nodes / block, 256 threads. Aggregation: warp w handles nodes w*8..w*8+7,
// lanes = 2 features each, results written straight into the sX GEMM tile.
// smem (floats): sH[128*68=8704] | union{ sX[64*68=4352] + sW1[8192] , sW2 }
#define SX_STRIDE 68
#define SH_STRIDE 68
#define SMEM_FLOATS (8704 + 4352 + 8192)   // 21248 floats = 84992 bytes

__global__ void __launch_bounds__(256, 2) conv_kernel(int cur, int last,
                                                      const float* __restrict__ W1,
                                                      const float* __restrict__ b1,
                                                      const float* __restrict__ W2,
                                                      const float* __restrict__ b2,
                                                      const float* __restrict__ eW,
                                                      const float* __restrict__ eb,
                                                      const int* __restrict__ batch) {
    extern __shared__ float sm[];
    float* sH  = sm;                 // [128][68]
    float* sX  = sm + 8704;          // [64][68]
    float* sW1 = sm + 8704 + 4352;   // [64][128]
    float* sW2 = sm + 8704;          // [128][64] phase-2 overlay

    int tid = threadIdx.x, lane = tid & 31, w = tid >> 5;
    int base = blockIdx.x * 64;
    const float* h_in  = cur ? g_h1 : g_h0;
    float*       h_out = cur ? g_h0 : g_h1;

    // load W1 while aggregation warps start
    {
        const float4* w4 = (const float4*)W1;
        float4* s4 = (float4*)sW1;
#pragma unroll
        for (int i = 0; i < 8; i++) s4[tid + i * 256] = w4[tid + i * 256];
    }

    // ---- aggregation into sX ----
    {
        float2 we0 = ((const float2*)(eW + 0 * 64))[lane];
        float2 we1 = ((const float2*)(eW + 1 * 64))[lane];
        float2 we2 = ((const float2*)(eW + 2 * 64))[lane];
        float2 we3 = ((const float2*)(eW + 3 * 64))[lane];
        float2 we4 = ((const float2*)(eW + 4 * 64))[lane];
        float2 we5 = ((const float2*)(eW + 5 * 64))[lane];
        float2 we6 = ((const float2*)(eW + 6 * 64))[lane];
        float2 bb  = ((const float2*)eb)[lane];
        float2 we7 = ((const float2*)(eW + 7 * 64))[lane];

#pragma unroll
        for (int j = 0; j < 8; j++) {
            int ln = w * 8 + j;
            int d = base + ln;
            float ox = 0.0f, oy = 0.0f;
            if (d < N_NODES) {
                int start = g_off[d];
                int cnt = g_deg[d];
                float den0 = 0.f, den1 = 0.f, num0 = 0.f, num1 = 0.f;
#pragma unroll 2
                for (int i = start; i < start + cnt; i++) {
                    int s = __ldg(g_src_s + i);
                    const float4* ap = (const float4*)(g_ea_s + (size_t)i * 8);
                    float4 a0 = __ldg(ap), a1 = __ldg(ap + 1);
                    float2 hv = *(const float2*)(h_in + (size_t)s * HDIM + 2 * lane);
                    float e0 = bb.x, e1 = bb.y;
                    e0 = fmaf(a0.x, we0.x, e0); e1 = fmaf(a0.x, we0.y, e1);
                    e0 = fmaf(a0.y, we1.x, e0); e1 = fmaf(a0.y, we1.y, e1);
                    e0 = fmaf(a0.z, we2.x, e0); e1 = fmaf(a0.z, we2.y, e1);
                    e0 = fmaf(a0.w, we3.x, e0); e1 = fmaf(a0.w, we3.y, e1);
                    e0 = fmaf(a1.x, we4.x, e0); e1 = fmaf(a1.x, we4.y, e1);
                    e0 = fmaf(a1.y, we5.x, e0); e1 = fmaf(a1.y, we5.y, e1);
                    e0 = fmaf(a1.z, we6.x, e0); e1 = fmaf(a1.z, we6.y, e1);
                    e0 = fmaf(a1.w, we7.x, e0); e1 = fmaf(a1.w, we7.y, e1);
                    float m0 = fmaxf(hv.x + e0, 0.0f) + EPSV;
                    float m1 = fmaxf(hv.y + e1, 0.0f) + EPSV;
                    float x0 = exp2f(fmaf(m0, LOG2E, -SHL2));
                    float x1 = exp2f(fmaf(m1, LOG2E, -SHL2));
                    den0 += x0; den1 += x1;
                    num0 = fmaf(m0, x0, num0);
                    num1 = fmaf(m1, x1, num1);
                }
                float2 hd = *(const float2*)(h_in + (size_t)d * HDIM + 2 * lane);
                ox = hd.x + num0 / fmaxf(den0, 1e-16f);
                oy = hd.y + num1 / fmaxf(den1, 1e-16f);
            }
            sX[(2 * lane) * SX_STRIDE + ln] = ox;
            sX[(2 * lane + 1) * SX_STRIDE + ln] = oy;
        }
    }
    __syncthreads();

    int nodeg = tid & 15;   // 4 nodes
    int hidg  = tid >> 4;   // 8 hidden = 4 packed pairs

    // ---- phase 1: hid = relu(x @ W1 + b1), packed f32x2 ----
    ull acc[4][4];
    {
        float4 ba = *(const float4*)&b1[hidg * 8];
        float4 bbv = *(const float4*)&b1[hidg * 8 + 4];
        ull p0 = pack2(ba.x, ba.y), p1 = pack2(ba.z, ba.w);
        ull p2 = pack2(bbv.x, bbv.y), p3 = pack2(bbv.z, bbv.w);
#pragma unroll
        for (int n = 0; n < 4; n++) { acc[n][0] = p0; acc[n][1] = p1; acc[n][2] = p2; acc[n][3] = p3; }
    }
#pragma unroll 4
    for (int k = 0; k < 64; k++) {
        float4 xv = *(const float4*)&sX[k * SX_STRIDE + nodeg * 4];
        ulonglong2 wA = *(const ulonglong2*)&sW1[k * 128 + hidg * 8];
        ulonglong2 wB = *(const ulonglong2*)&sW1[k * 128 + hidg * 8 + 4];
        float xs[4] = { xv.x, xv.y, xv.z, xv.w };
#pragma unroll
        for (int n = 0; n < 4; n++) {
            ull xd = pack2(xs[n], xs[n]);
            fma2(acc[n][0], xd, wA.x);
            fma2(acc[n][1], xd, wA.y);
            fma2(acc[n][2], xd, wB.x);
            fma2(acc[n][3], xd, wB.y);
        }
    }
#pragma unroll
    for (int p = 0; p < 4; p++) {
        float lo[4], hi[4];
#pragma unroll
        for (int n = 0; n < 4; n++) unpack2(lo[n], hi[n], acc[n][p]);
        *(float4*)&sH[(hidg * 8 + 2 * p) * SH_STRIDE + nodeg * 4] =
            make_float4(fmaxf(lo[0], 0.f), fmaxf(lo[1], 0.f), fmaxf(lo[2], 0.f), fmaxf(lo[3], 0.f));
        *(float4*)&sH[(hidg * 8 + 2 * p + 1) * SH_STRIDE + nodeg * 4] =
            make_float4(fmaxf(hi[0], 0.f), fmaxf(hi[1], 0.f), fmaxf(hi[2], 0.f), fmaxf(hi[3], 0.f));
    }
    __syncthreads();

    // load W2 into overlay region
    {
        const float4* w4 = (const float4*)W2;
        float4* s4 = (float4*)sW2;
#pragma unroll
        for (int i = 0; i < 8; i++) s4[tid + i * 256] = w4[tid + i * 256];
    }
    __syncthreads();

    // ---- phase 2: out = relu(hid @ W2 + b2), packed f32x2 ----
    int outg = tid >> 4;   // 4 outputs = 2 packed pairs
    ull a2[4][2];
    {
        float4 bv = *(const float4*)&b2[outg * 4];
        ull p0 = pack2(bv.x, bv.y), p1 = pack2(bv.z, bv.w);
#pragma unroll
        for (int n = 0; n < 4; n++) { a2[n][0] = p0; a2[n][1] = p1; }
    }
#pragma unroll 4
    for (int k = 0; k < 128; k++) {
        float4 hv = *(const float4*)&sH[k * SH_STRIDE + nodeg * 4];
        ulonglong2 wp = *(const ulonglong2*)&sW2[k * 64 + outg * 4];
        float hs[4] = { hv.x, hv.y, hv.z, hv.w };
#pragma unroll
        for (int n = 0; n < 4; n++) {
            ull xd = pack2(hs[n], hs[n]);
            fma2(a2[n][0], xd, wp.x);
            fma2(a2[n][1], xd, wp.y);
        }
    }
#pragma unroll
    for (int n = 0; n < 4; n++) {
        int gn = base + nodeg * 4 + n;
        if (gn < N_NODES) {
            float r0, r1, r2, r3;
            unpack2(r0, r1, a2[n][0]);
            unpack2(r2, r3, a2[n][1]);
            r0 = fmaxf(r0, 0.f); r1 = fmaxf(r1, 0.f);
            r2 = fmaxf(r2, 0.f); r3 = fmaxf(r3, 0.f);
            if (last) {
                int b = __ldg(batch + gn);
                red4(g_pool + (size_t)b * HDIM + outg * 4, r0, r1, r2, r3);
            } else {
                *(float4*)&h_out[(size_t)gn * HDIM + outg * 4] = make_float4(r0, r1, r2, r3);
            }
        }
    }
}

// ---------------- graph head --------------------------------------------------
__global__ void __launch_bounds__(256) head_kernel(const float* __restrict__ graph_attr,
                                                   const float* __restrict__ d1W, const float* __restrict__ d1b,
                                                   const float* __restrict__ d2W, const float* __restrict__ d2b,
                                                   const float* __restrict__ oW,  const float* __restrict__ ob,
                                                   float* __restrict__ out) {
    int t = blockIdx.x * 256 + threadIdx.x;
    int g = t >> 5, lane = t & 31;
    if (g >= N_GRAPHS) return;
    float cnt = fmaxf(g_cnt[g], 1.0f);
    float p0 = g_pool[g * HDIM + lane] / cnt;
    float p1 = g_pool[g * HDIM + 32 + lane] / cnt;
    float ga = (lane < 10) ? graph_attr[g * 10 + lane] : 0.0f;

    float a = d1b[lane];
#pragma unroll
    for (int k = 0; k < 32; k++) a = fmaf(__shfl_sync(0xffffffffu, p0, k), d1W[k * 32 + lane], a);
#pragma unroll
    for (int k = 0; k < 32; k++) a = fmaf(__shfl_sync(0xffffffffu, p1, k), d1W[(32 + k) * 32 + lane], a);
#pragma unroll
    for (int k = 0; k < 10; k++) a = fmaf(__shfl_sync(0xffffffffu, ga, k), d1W[(64 + k) * 32 + lane], a);
    a = fmaxf(a, 0.0f);

    float bsum = d2b[lane];
#pragma unroll
    for (int k = 0; k < 32; k++) bsum = fmaf(__shfl_sync(0xffffffffu, a, k), d2W[k * 32 + lane], bsum);
    bsum = fmaxf(bsum, 0.0f);

    float v = bsum * oW[lane];
#pragma unroll
    for (int s = 16; s > 0; s >>= 1) v += __shfl_xor_sync(0xffffffffu, v, s);
    if (lane == 0) out[g] = 1.0f / (1.0f + expf(-(v + ob[0])));
}

// ---------------- launch -------------------------------------------------------
extern "C" void kernel_launch(void* const* d_in, const int* in_sizes, int n_in,
                              void* d_out, int out_size) {
    const float* x          = (const float*)d_in[0];
    const float* edge_attr  = (const float*)d_in[1];
    const float* graph_attr = (const float*)d_in[2];
    const int*   edge_index = (const int*)d_in[3];
    const int*   batch      = (const int*)d_in[4];
    const float* node_W     = (const float*)d_in[5];
    const float* node_b     = (const float*)d_in[6];
    const float* edge_W     = (const float*)d_in[7];
    const float* edge_b     = (const float*)d_in[8];
    const float* cW1[3] = { (const float*)d_in[9],  (const float*)d_in[13], (const float*)d_in[17] };
    const float* cb1[3] = { (const float*)d_in[10], (const float*)d_in[14], (const float*)d_in[18] };
    const float* cW2[3] = { (const float*)d_in[11], (const float*)d_in[15], (const float*)d_in[19] };
    const float* cb2[3] = { (const float*)d_in[12], (const float*)d_in[16], (const float*)d_in[20] };
    const float* d1W = (const float*)d_in[21];
    const float* d1b = (const float*)d_in[22];
    const float* d2W = (const float*)d_in[23];
    const float* d2b = (const float*)d_in[24];
    const float* oW  = (const float*)d_in[25];
    const float* ob  = (const float*)d_in[26];
    const int* esrc = edge_index;
    const int* edst = edge_index + N_EDGES;
    float* out = (float*)d_out;

    const int SMEM_CONV = SMEM_FLOATS * 4;   // 84992 bytes
    cudaFuncSetAttribute((const void*)conv_kernel,
                         cudaFuncAttributeMaxDynamicSharedMemorySize, SMEM_CONV);

    zero_small<<<(N_NODES + 255) / 256, 256>>>();
    input_proj<<<(N_NODES * 16) / 256, 256>>>(x, node_W, node_b);

    // CSR build (once, reused by all 3 convs)
    hist_kernel<<<(N_EDGES + 255) / 256, 256>>>(edst);
    scan1_kernel<<<NSCAN, SCAN_BLK>>>();
    scan2_kernel<<<1, 256>>>();
    scan3_kernel<<<(N_NODES + 255) / 256, 256>>>(batch);
    scatter_kernel<<<(N_EDGES + 255) / 256, 256>>>(edge_attr, esrc, edst);

    int cur = 0;
    const int NBLK = (N_NODES + 63) / 64;
    for (int c = 0; c < 3; c++) {
        conv_kernel<<<NBLK, 256, SMEM_CONV>>>(cur, (c == 2) ? 1 : 0,
                                              cW1[c], cb1[c], cW2[c], cb2[c],
                                              edge_W, edge_b, batch);
        cur ^= 1;
    }

    head_kernel<<<(N_GRAPHS * 32) / 256, 256>>>(graph_attr, d1W, d1b, d2W, d2b, oW, ob, out);
}

// round 4
// speedup vs baseline: 1.2334x; 1.2334x over previous
#include <cuda_runtime.h>
#include <math.h>

#define N_NODES   100000
#define N_EDGES   1600000
#define N_GRAPHS  1024
#define HDIM      64
#define EPSV      1e-7f
#define LOG2E     1.4426950408889634f
#define SHL2      57.707801635558536f   /* 40 * log2(e) */
#define SCAN_BLK  512
#define NSCAN     ((N_NODES + SCAN_BLK - 1) / SCAN_BLK)   // 196

typedef unsigned long long ull;

// ---------------- scratch (static device globals; no allocation) -------------
__device__ float g_h0[N_NODES * HDIM];
__device__ float g_h1[N_NODES * HDIM];
__device__ float g_agg[N_NODES * HDIM];
__device__ float g_pool[N_GRAPHS * HDIM];
__device__ float g_cnt[N_GRAPHS];
// CSR
__device__ int   g_deg[N_NODES];
__device__ int   g_off[N_NODES];
__device__ int   g_cursor[N_NODES];
__device__ int   g_bsum[NSCAN];
__device__ int   g_src_s[N_EDGES];
__device__ float g_ea_s[(size_t)N_EDGES * 8];

__device__ __forceinline__ void red4(float* p, float a, float b, float c, float d) {
    asm volatile("red.global.add.v4.f32 [%0], {%1,%2,%3,%4};"
                 :: "l"(p), "f"(a), "f"(b), "f"(c), "f"(d) : "memory");
}
__device__ __forceinline__ ull pack2(float x, float y) {
    ull r; asm("mov.b64 %0, {%1, %2};" : "=l"(r) : "f"(x), "f"(y)); return r;
}
__device__ __forceinline__ void unpack2(float& x, float& y, ull v) {
    asm("mov.b64 {%0, %1}, %2;" : "=f"(x), "=f"(y) : "l"(v));
}
__device__ __forceinline__ void fma2(ull& d, ull a, ull b) {
    asm("fma.rn.f32x2 %0, %1, %2, %0;" : "+l"(d) : "l"(a), "l"(b));
}

// ---------------- h0 = x @ node_W + node_b  (16 -> 64), + zero scratch --------
__global__ void __launch_bounds__(256) input_proj(const float* __restrict__ x,
                                                  const float* __restrict__ W,
                                                  const float* __restrict__ b) {
    __shared__ float4 sW[256];
    __shared__ float4 sb[16];
    int tid = threadIdx.x;
    sW[tid] = ((const float4*)W)[tid];
    if (tid < 16) sb[tid] = ((const float4*)b)[tid];
    __syncthreads();

    int t = blockIdx.x * 256 + tid;
    // fused zeroing (grid = 1.6M threads covers all)
    if (t < N_NODES) g_deg[t] = 0;
    if (t < N_GRAPHS * HDIM) g_pool[t] = 0.0f;
    if (t < N_GRAPHS) g_cnt[t] = 0.0f;

    int n = t >> 4, g = t & 15;
    if (n >= N_NODES) return;
    const float4* xr = (const float4*)(x + n * 16);
    float4 x0 = xr[0], x1 = xr[1], x2 = xr[2], x3 = xr[3];
    float4 acc = sb[g];
#define ISTEP(av, kk) { float4 w = sW[(kk)*16 + g]; \
    acc.x = fmaf(av, w.x, acc.x); acc.y = fmaf(av, w.y, acc.y); \
    acc.z = fmaf(av, w.z, acc.z); acc.w = fmaf(av, w.w, acc.w); }
    ISTEP(x0.x, 0)  ISTEP(x0.y, 1)  ISTEP(x0.z, 2)  ISTEP(x0.w, 3)
    ISTEP(x1.x, 4)  ISTEP(x1.y, 5)  ISTEP(x1.z, 6)  ISTEP(x1.w, 7)
    ISTEP(x2.x, 8)  ISTEP(x2.y, 9)  ISTEP(x2.z, 10) ISTEP(x2.w, 11)
    ISTEP(x3.x, 12) ISTEP(x3.y, 13) ISTEP(x3.z, 14) ISTEP(x3.w, 15)
#undef ISTEP
    ((float4*)(g_h0 + (size_t)n * HDIM))[g] = acc;
}

// ---------------- CSR build ----------------------------------------------------
__global__ void __launch_bounds__(256) hist_kernel(const int* __restrict__ edst) {
    int e = blockIdx.x * 256 + threadIdx.x;
    if (e < N_EDGES) atomicAdd(&g_deg[edst[e]], 1);
}

__global__ void __launch_bounds__(SCAN_BLK) scan1_kernel() {
    __shared__ int wsum[SCAN_BLK / 32];
    int d = blockIdx.x * SCAN_BLK + threadIdx.x;
    int v = (d < N_NODES) ? g_deg[d] : 0;
    int lane = threadIdx.x & 31, w = threadIdx.x >> 5;
    int inc = v;
#pragma unroll
    for (int o = 1; o < 32; o <<= 1) {
        int t = __shfl_up_sync(0xffffffffu, inc, o);
        if (lane >= o) inc += t;
    }
    if (lane == 31) wsum[w] = inc;
    __syncthreads();
    if (w == 0) {
        int s = (lane < SCAN_BLK / 32) ? wsum[lane] : 0;
#pragma unroll
        for (int o = 1; o < 16; o <<= 1) {
            int t = __shfl_up_sync(0xffffffffu, s, o);
            if (lane >= o) s += t;
        }
        if (lane < SCAN_BLK / 32) wsum[lane] = s;
    }
    __syncthreads();
    int base = (w > 0) ? wsum[w - 1] : 0;
    if (d < N_NODES) g_off[d] = base + inc - v;
    if (threadIdx.x == SCAN_BLK - 1) g_bsum[blockIdx.x] = base + inc;
}

// merged scan2+scan3: each 256-node block sums its prefix of block totals itself
__global__ void __launch_bounds__(256) scan23_kernel(const int* __restrict__ batch) {
    __shared__ int sP;
    int b = blockIdx.x;
    int sb = b >> 1;   // which scan1 block this 256-chunk belongs to (256 | 512)
    if (threadIdx.x < 32) {
        int p = 0;
        for (int j = threadIdx.x; j < sb; j += 32) p += g_bsum[j];
#pragma unroll
        for (int o = 16; o; o >>= 1) p += __shfl_xor_sync(0xffffffffu, p, o);
        if (threadIdx.x == 0) sP = p;
    }
    __syncthreads();
    int d = b * 256 + threadIdx.x;
    if (d < N_NODES) {
        int o = g_off[d] + sP;
        g_off[d] = o;
        g_cursor[d] = o;
        atomicAdd(&g_cnt[batch[d]], 1.0f);   // per-graph node counts (once)
    }
}

__global__ void __launch_bounds__(256) scatter_kernel(const float* __restrict__ edge_attr,
                                                      const int* __restrict__ esrc,
                                                      const int* __restrict__ edst) {
    int e = blockIdx.x * 256 + threadIdx.x;
    if (e >= N_EDGES) return;
    int d = edst[e];
    int pos = atomicAdd(&g_cursor[d], 1);
    const float4* a = (const float4*)(edge_attr + (size_t)e * 8);
    float4 a0 = __ldg(a), a1 = __ldg(a + 1);
    g_src_s[pos] = esrc[e];
    float4* o = (float4*)(g_ea_s + (size_t)pos * 8);
    o[0] = a0; o[1] = a1;
}

// ---------------- per-dst aggregation (warp per dst, 4-deep pipeline) ----------
__global__ void __launch_bounds__(256) agg_pass(int cur,
                                                const float* __restrict__ eW,
                                                const float* __restrict__ eb) {
    int lane = threadIdx.x & 31;
    int d = blockIdx.x * 8 + (threadIdx.x >> 5);   // grid 12500 exact
    const float* h = cur ? g_h1 : g_h0;

    float2 w0 = ((const float2*)(eW + 0 * 64))[lane];
    float2 w1 = ((const float2*)(eW + 1 * 64))[lane];
    float2 w2 = ((const float2*)(eW + 2 * 64))[lane];
    float2 w3 = ((const float2*)(eW + 3 * 64))[lane];
    float2 w4 = ((const float2*)(eW + 4 * 64))[lane];
    float2 w5 = ((const float2*)(eW + 5 * 64))[lane];
    float2 w6 = ((const float2*)(eW + 6 * 64))[lane];
    float2 w7 = ((const float2*)(eW + 7 * 64))[lane];
    float2 bb = ((const float2*)eb)[lane];

    int start = g_off[d];
    int end = start + g_deg[d];
    float den0 = 0.f, den1 = 0.f, num0 = 0.f, num1 = 0.f;

#define EDGE_BODY(A0, A1, HV) { \
    float e0 = bb.x, e1 = bb.y; \
    e0 = fmaf(A0.x, w0.x, e0); e1 = fmaf(A0.x, w0.y, e1); \
    e0 = fmaf(A0.y, w1.x, e0); e1 = fmaf(A0.y, w1.y, e1); \
    e0 = fmaf(A0.z, w2.x, e0); e1 = fmaf(A0.z, w2.y, e1); \
    e0 = fmaf(A0.w, w3.x, e0); e1 = fmaf(A0.w, w3.y, e1); \
    e0 = fmaf(A1.x, w4.x, e0); e1 = fmaf(A1.x, w4.y, e1); \
    e0 = fmaf(A1.y, w5.x, e0); e1 = fmaf(A1.y, w5.y, e1); \
    e0 = fmaf(A1.z, w6.x, e0); e1 = fmaf(A1.z, w6.y, e1); \
    e0 = fmaf(A1.w, w7.x, e0); e1 = fmaf(A1.w, w7.y, e1); \
    float m0 = fmaxf(HV.x + e0, 0.0f) + EPSV; \
    float m1 = fmaxf(HV.y + e1, 0.0f) + EPSV; \
    float x0 = exp2f(fmaf(m0, LOG2E, -SHL2)); \
    float x1 = exp2f(fmaf(m1, LOG2E, -SHL2)); \
    den0 += x0; den1 += x1; \
    num0 = fmaf(m0, x0, num0); \
    num1 = fmaf(m1, x1, num1); }

    int i = start;
    for (; i + 4 <= end; i += 4) {
        // front-batch loads: 4 src, 8 ea, then 4 dependent h gathers (MLP=4)
        int s0 = __ldg(g_src_s + i), s1 = __ldg(g_src_s + i + 1);
        int s2 = __ldg(g_src_s + i + 2), s3 = __ldg(g_src_s + i + 3);
        const float4* ap = (const float4*)(g_ea_s + (size_t)i * 8);
        float4 a00 = __ldg(ap + 0), a01 = __ldg(ap + 1);
        float4 a10 = __ldg(ap + 2), a11 = __ldg(ap + 3);
        float4 a20 = __ldg(ap + 4), a21 = __ldg(ap + 5);
        float4 a30 = __ldg(ap + 6), a31 = __ldg(ap + 7);
        float2 h0 = *(const float2*)(h + (size_t)s0 * HDIM + 2 * lane);
        float2 h1 = *(const float2*)(h + (size_t)s1 * HDIM + 2 * lane);
        float2 h2 = *(const float2*)(h + (size_t)s2 * HDIM + 2 * lane);
        float2 h3 = *(const float2*)(h + (size_t)s3 * HDIM + 2 * lane);
        EDGE_BODY(a00, a01, h0)
        EDGE_BODY(a10, a11, h1)
        EDGE_BODY(a20, a21, h2)
        EDGE_BODY(a30, a31, h3)
    }
    for (; i < end; i++) {
        int s = __ldg(g_src_s + i);
        const float4* ap = (const float4*)(g_ea_s + (size_t)i * 8);
        float4 a0 = __ldg(ap), a1 = __ldg(ap + 1);
        float2 hv = *(const float2*)(h + (size_t)s * HDIM + 2 * lane);
        EDGE_BODY(a0, a1, hv)
    }
#undef EDGE_BODY

    float2 out;
    out.x = num0 / fmaxf(den0, 1e-16f);
    out.y = num1 / fmaxf(den1, 1e-16f);
    *(float2*)(g_agg + (size_t)d * HDIM + 2 * lane) = out;
}

// ---------------- node MLP: smem-tiled GEMM, packed f32x2 (+pool on last) ------
#define SX_STRIDE 68
#define SH_STRIDE 68
#define SMEM_FLOATS (8704 + 4352 + 8192)   // 21248 floats = 84992 bytes

__global__ void __launch_bounds__(256, 2) node_mlp(int cur, int last,
                                                   const float* __restrict__ W1,
                                                   const float* __restrict__ b1,
                                                   const float* __restrict__ W2,
                                                   const float* __restrict__ b2,
                                                   const int* __restrict__ batch) {
    extern __shared__ float sm[];
    float* sH  = sm;                 // [128][68]
    float* sX  = sm + 8704;          // [64][68]
    float* sW1 = sm + 8704 + 4352;   // [64][128]
    float* sW2 = sm + 8704;          // [128][64] phase-2 overlay

    int tid = threadIdx.x;
    int base = blockIdx.x * 64;
    const float* h_in  = cur ? g_h1 : g_h0;
    float*       h_out = cur ? g_h0 : g_h1;

    {
        const float4* w4 = (const float4*)W1;
        float4* s4 = (float4*)sW1;
#pragma unroll
        for (int i = 0; i < 8; i++) s4[tid + i * 256] = w4[tid + i * 256];
    }
    for (int idx = tid; idx < 64 * 64; idx += 256) {
        int n = idx >> 6, f = idx & 63;
        int gn = base + n;
        float v = 0.0f;
        if (gn < N_NODES)
            v = h_in[(size_t)gn * HDIM + f] + g_agg[(size_t)gn * HDIM + f];
        sX[f * SX_STRIDE + n] = v;
    }
    __syncthreads();

    int nodeg = tid & 15;   // 4 nodes
    int hidg  = tid >> 4;   // 8 hidden = 4 packed pairs

    // ---- phase 1: hid = relu(x @ W1 + b1), packed f32x2 ----
    ull acc[4][4];
    {
        float4 ba = *(const float4*)&b1[hidg * 8];
        float4 bbv = *(const float4*)&b1[hidg * 8 + 4];
        ull p0 = pack2(ba.x, ba.y), p1 = pack2(ba.z, ba.w);
        ull p2 = pack2(bbv.x, bbv.y), p3 = pack2(bbv.z, bbv.w);
#pragma unroll
        for (int n = 0; n < 4; n++) { acc[n][0] = p0; acc[n][1] = p1; acc[n][2] = p2; acc[n][3] = p3; }
    }
#pragma unroll 4
    for (int k = 0; k < 64; k++) {
        float4 xv = *(const float4*)&sX[k * SX_STRIDE + nodeg * 4];
        ulonglong2 wA = *(const ulonglong2*)&sW1[k * 128 + hidg * 8];
        ulonglong2 wB = *(const ulonglong2*)&sW1[k * 128 + hidg * 8 + 4];
        float xs[4] = { xv.x, xv.y, xv.z, xv.w };
#pragma unroll
        for (int n = 0; n < 4; n++) {
            ull xd = pack2(xs[n], xs[n]);
            fma2(acc[n][0], xd, wA.x);
            fma2(acc[n][1], xd, wA.y);
            fma2(acc[n][2], xd, wB.x);
            fma2(acc[n][3], xd, wB.y);
        }
    }
#pragma unroll
    for (int p = 0; p < 4; p++) {
        float lo[4], hi[4];
#pragma unroll
        for (int n = 0; n < 4; n++) unpack2(lo[n], hi[n], acc[n][p]);
        *(float4*)&sH[(hidg * 8 + 2 * p) * SH_STRIDE + nodeg * 4] =
            make_float4(fmaxf(lo[0], 0.f), fmaxf(lo[1], 0.f), fmaxf(lo[2], 0.f), fmaxf(lo[3], 0.f));
        *(float4*)&sH[(hidg * 8 + 2 * p + 1) * SH_STRIDE + nodeg * 4] =
            make_float4(fmaxf(hi[0], 0.f), fmaxf(hi[1], 0.f), fmaxf(hi[2], 0.f), fmaxf(hi[3], 0.f));
    }
    __syncthreads();

    {
        const float4* w4 = (const float4*)W2;
        float4* s4 = (float4*)sW2;
#pragma unroll
        for (int i = 0; i < 8; i++) s4[tid + i * 256] = w4[tid + i * 256];
    }
    __syncthreads();

    // ---- phase 2: out = relu(hid @ W2 + b2), packed f32x2 ----
    int outg = tid >> 4;
    ull a2[4][2];
    {
        float4 bv = *(const float4*)&b2[outg * 4];
        ull p0 = pack2(bv.x, bv.y), p1 = pack2(bv.z, bv.w);
#pragma unroll
        for (int n = 0; n < 4; n++) { a2[n][0] = p0; a2[n][1] = p1; }
    }
#pragma unroll 4
    for (int k = 0; k < 128; k++) {
        float4 hv = *(const float4*)&sH[k * SH_STRIDE + nodeg * 4];
        ulonglong2 wp = *(const ulonglong2*)&sW2[k * 64 + outg * 4];
        float hs[4] = { hv.x, hv.y, hv.z, hv.w };
#pragma unroll
        for (int n = 0; n < 4; n++) {
            ull xd = pack2(hs[n], hs[n]);
            fma2(a2[n][0], xd, wp.x);
            fma2(a2[n][1], xd, wp.y);
        }
    }
#pragma unroll
    for (int n = 0; n < 4; n++) {
        int gn = base + nodeg * 4 + n;
        if (gn < N_NODES) {
            float r0, r1, r2, r3;
            unpack2(r0, r1, a2[n][0]);
            unpack2(r2, r3, a2[n][1]);
            r0 = fmaxf(r0, 0.f); r1 = fmaxf(r1, 0.f);
            r2 = fmaxf(r2, 0.f); r3 = fmaxf(r3, 0.f);
            if (last) {
                int b = __ldg(batch + gn);
                red4(g_pool + (size_t)b * HDIM + outg * 4, r0, r1, r2, r3);
            } else {
                *(float4*)&h_out[(size_t)gn * HDIM + outg * 4] = make_float4(r0, r1, r2, r3);
            }
        }
    }
}

// ---------------- graph head --------------------------------------------------
__global__ void __launch_bounds__(256) head_kernel(const float* __restrict__ graph_attr,
                                                   const float* __restrict__ d1W, const float* __restrict__ d1b,
                                                   const float* __restrict__ d2W, const float* __restrict__ d2b,
                                                   const float* __restrict__ oW,  const float* __restrict__ ob,
                                                   float* __restrict__ out) {
    int t = blockIdx.x * 256 + threadIdx.x;
    int g = t >> 5, lane = t & 31;
    if (g >= N_GRAPHS) return;
    float cnt = fmaxf(g_cnt[g], 1.0f);
    float p0 = g_pool[g * HDIM + lane] / cnt;
    float p1 = g_pool[g * HDIM + 32 + lane] / cnt;
    float ga = (lane < 10) ? graph_attr[g * 10 + lane] : 0.0f;

    float a = d1b[lane];
#pragma unroll
    for (int k = 0; k < 32; k++) a = fmaf(__shfl_sync(0xffffffffu, p0, k), d1W[k * 32 + lane], a);
#pragma unroll
    for (int k = 0; k < 32; k++) a = fmaf(__shfl_sync(0xffffffffu, p1, k), d1W[(32 + k) * 32 + lane], a);
#pragma unroll
    for (int k = 0; k < 10; k++) a = fmaf(__shfl_sync(0xffffffffu, ga, k), d1W[(64 + k) * 32 + lane], a);
    a = fmaxf(a, 0.0f);

    float bsum = d2b[lane];
#pragma unroll
    for (int k = 0; k < 32; k++) bsum = fmaf(__shfl_sync(0xffffffffu, a, k), d2W[k * 32 + lane], bsum);
    bsum = fmaxf(bsum, 0.0f);

    float v = bsum * oW[lane];
#pragma unroll
    for (int s = 16; s > 0; s >>= 1) v += __shfl_xor_sync(0xffffffffu, v, s);
    if (lane == 0) out[g] = 1.0f / (1.0f + expf(-(v + ob[0])));
}

// ---------------- launch -------------------------------------------------------
extern "C" void kernel_launch(void* const* d_in, const int* in_sizes, int n_in,
                              void* d_out, int out_size) {
    const float* x          = (const float*)d_in[0];
    const float* edge_attr  = (const float*)d_in[1];
    const float* graph_attr = (const float*)d_in[2];
    const int*   edge_index = (const int*)d_in[3];
    const int*   batch      = (const int*)d_in[4];
    const float* node_W     = (const float*)d_in[5];
    const float* node_b     = (const float*)d_in[6];
    const float* edge_W     = (const float*)d_in[7];
    const float* edge_b     = (const float*)d_in[8];
    const float* cW1[3] = { (const float*)d_in[9],  (const float*)d_in[13], (const float*)d_in[17] };
    const float* cb1[3] = { (const float*)d_in[10], (const float*)d_in[14], (const float*)d_in[18] };
    const float* cW2[3] = { (const float*)d_in[11], (const float*)d_in[15], (const float*)d_in[19] };
    const float* cb2[3] = { (const float*)d_in[12], (const float*)d_in[16], (const float*)d_in[20] };
    const float* d1W = (const float*)d_in[21];
    const float* d1b = (const float*)d_in[22];
    const float* d2W = (const float*)d_in[23];
    const float* d2b = (const float*)d_in[24];
    const float* oW  = (const float*)d_in[25];
    const float* ob  = (const float*)d_in[26];
    const int* esrc = edge_index;
    const int* edst = edge_index + N_EDGES;
    float* out = (float*)d_out;

    const int SMEM_MLP = SMEM_FLOATS * 4;   // 84992 bytes
    cudaFuncSetAttribute((const void*)node_mlp,
                         cudaFuncAttributeMaxDynamicSharedMemorySize, SMEM_MLP);

    // 1
    input_proj<<<(N_NODES * 16) / 256, 256>>>(x, node_W, node_b);
    // 2-5: CSR build (once, reused by all 3 convs)
    hist_kernel<<<(N_EDGES + 255) / 256, 256>>>(edst);
    scan1_kernel<<<NSCAN, SCAN_BLK>>>();
    scan23_kernel<<<(N_NODES + 255) / 256, 256>>>(batch);
    scatter_kernel<<<(N_EDGES + 255) / 256, 256>>>(edge_attr, esrc, edst);

    int cur = 0;
    const int NBLK_MLP = (N_NODES + 63) / 64;
    for (int c = 0; c < 3; c++) {
        // launch #6 on c==0: agg_pass — lands in the ncu capture slot
        agg_pass<<<N_NODES / 8, 256>>>(cur, edge_W, edge_b);
        node_mlp<<<NBLK_MLP, 256, SMEM_MLP>>>(cur, (c == 2) ? 1 : 0,
                                              cW1[c], cb1[c], cW2[c], cb2[c], batch);
        cur ^= 1;
    }

    head_kernel<<<(N_GRAPHS * 32) / 256, 256>>>(graph_attr, d1W, d1b, d2W, d2b, oW, ob, out);
}

// round 5
// speedup vs baseline: 1.2600x; 1.0216x over previous
#include <cuda_runtime.h>
#include <math.h>

#define N_NODES   100000
#define N_EDGES   1600000
#define N_GRAPHS  1024
#define HDIM      64
#define EPSV      1e-7f
#define LOG2E     1.4426950408889634f
#define SHL2      57.707801635558536f   /* 40 * log2(e) */
#define SCAN_BLK  512
#define NSCAN     ((N_NODES + SCAN_BLK - 1) / SCAN_BLK)   // 196

typedef unsigned long long ull;

// ---------------- scratch (static device globals; no allocation) -------------
// g_deg invariant: zero at kernel_launch entry (.bss at load; re-zeroed by
// head_kernel at the end of every call) — hist accumulates into it directly.
__device__ float g_h0[N_NODES * HDIM];
__device__ float g_h1[N_NODES * HDIM];
__device__ float g_agg[N_NODES * HDIM];
__device__ float g_pool[N_GRAPHS * HDIM];
__device__ float g_cnt[N_GRAPHS];
__device__ int   g_deg[N_NODES];
__device__ int   g_off[N_NODES];
__device__ int   g_cursor[N_NODES];
__device__ int   g_bsum[NSCAN];
__device__ int   g_src_s[N_EDGES];
__device__ float g_ea_s[(size_t)N_EDGES * 8];

__device__ __forceinline__ void red4(float* p, float a, float b, float c, float d) {
    asm volatile("red.global.add.v4.f32 [%0], {%1,%2,%3,%4};"
                 :: "l"(p), "f"(a), "f"(b), "f"(c), "f"(d) : "memory");
}
__device__ __forceinline__ ull pack2(float x, float y) {
    ull r; asm("mov.b64 %0, {%1, %2};" : "=l"(r) : "f"(x), "f"(y)); return r;
}
__device__ __forceinline__ void unpack2(float& x, float& y, ull v) {
    asm("mov.b64 {%0, %1}, %2;" : "=f"(x), "=f"(y) : "l"(v));
}
__device__ __forceinline__ void fma2(ull& d, ull a, ull b) {
    asm("fma.rn.f32x2 %0, %1, %2, %0;" : "+l"(d) : "l"(a), "l"(b));
}
__device__ __forceinline__ ull fma2_3(ull a, ull b, ull c) {
    ull d; asm("fma.rn.f32x2 %0, %1, %2, %3;" : "=l"(d) : "l"(a), "l"(b), "l"(c)); return d;
}
__device__ __forceinline__ ull add2(ull a, ull b) {
    ull d; asm("add.rn.f32x2 %0, %1, %2;" : "=l"(d) : "l"(a), "l"(b)); return d;
}
__device__ __forceinline__ ull splat(float v) { return pack2(v, v); }

// ------- h0 = x @ node_W + node_b (16->64), fused hist + scratch zeroing ------
__global__ void __launch_bounds__(256) input_proj(const float* __restrict__ x,
                                                  const float* __restrict__ W,
                                                  const float* __restrict__ b,
                                                  const int* __restrict__ edst) {
    __shared__ float4 sW[256];
    __shared__ float4 sb[16];
    int tid = threadIdx.x;
    sW[tid] = ((const float4*)W)[tid];
    if (tid < 16) sb[tid] = ((const float4*)b)[tid];
    __syncthreads();

    int t = blockIdx.x * 256 + tid;   // grid covers exactly N_EDGES threads
    // fused degree histogram (g_deg is zero at entry by invariant)
    atomicAdd(&g_deg[__ldg(edst + t)], 1);
    if (t < N_GRAPHS * HDIM) g_pool[t] = 0.0f;
    if (t < N_GRAPHS) g_cnt[t] = 0.0f;

    int n = t >> 4, g = t & 15;
    if (n >= N_NODES) return;
    const float4* xr = (const float4*)(x + n * 16);
    float4 x0 = xr[0], x1 = xr[1], x2 = xr[2], x3 = xr[3];
    float4 acc = sb[g];
#define ISTEP(av, kk) { float4 w = sW[(kk)*16 + g]; \
    acc.x = fmaf(av, w.x, acc.x); acc.y = fmaf(av, w.y, acc.y); \
    acc.z = fmaf(av, w.z, acc.z); acc.w = fmaf(av, w.w, acc.w); }
    ISTEP(x0.x, 0)  ISTEP(x0.y, 1)  ISTEP(x0.z, 2)  ISTEP(x0.w, 3)
    ISTEP(x1.x, 4)  ISTEP(x1.y, 5)  ISTEP(x1.z, 6)  ISTEP(x1.w, 7)
    ISTEP(x2.x, 8)  ISTEP(x2.y, 9)  ISTEP(x2.z, 10) ISTEP(x2.w, 11)
    ISTEP(x3.x, 12) ISTEP(x3.y, 13) ISTEP(x3.z, 14) ISTEP(x3.w, 15)
#undef ISTEP
    ((float4*)(g_h0 + (size_t)n * HDIM))[g] = acc;
}

// ---------------- CSR scans ----------------------------------------------------
__global__ void __launch_bounds__(SCAN_BLK) scan1_kernel() {
    __shared__ int wsum[SCAN_BLK / 32];
    int d = blockIdx.x * SCAN_BLK + threadIdx.x;
    int v = (d < N_NODES) ? g_deg[d] : 0;
    int lane = threadIdx.x & 31, w = threadIdx.x >> 5;
    int inc = v;
#pragma unroll
    for (int o = 1; o < 32; o <<= 1) {
        int t = __shfl_up_sync(0xffffffffu, inc, o);
        if (lane >= o) inc += t;
    }
    if (lane == 31) wsum[w] = inc;
    __syncthreads();
    if (w == 0) {
        int s = (lane < SCAN_BLK / 32) ? wsum[lane] : 0;
#pragma unroll
        for (int o = 1; o < 16; o <<= 1) {
            int t = __shfl_up_sync(0xffffffffu, s, o);
            if (lane >= o) s += t;
        }
        if (lane < SCAN_BLK / 32) wsum[lane] = s;
    }
    __syncthreads();
    int base = (w > 0) ? wsum[w - 1] : 0;
    if (d < N_NODES) g_off[d] = base + inc - v;
    if (threadIdx.x == SCAN_BLK - 1) g_bsum[blockIdx.x] = base + inc;
}

__global__ void __launch_bounds__(256) scan23_kernel(const int* __restrict__ batch) {
    __shared__ int sP;
    int b = blockIdx.x;
    int sb = b >> 1;
    if (threadIdx.x < 32) {
        int p = 0;
        for (int j = threadIdx.x; j < sb; j += 32) p += g_bsum[j];
#pragma unroll
        for (int o = 16; o; o >>= 1) p += __shfl_xor_sync(0xffffffffu, p, o);
        if (threadIdx.x == 0) sP = p;
    }
    __syncthreads();
    int d = b * 256 + threadIdx.x;
    int bg = (d < N_NODES) ? __ldg(batch + d) : -1;
    if (d < N_NODES) {
        int o = g_off[d] + sP;
        g_off[d] = o;
        g_cursor[d] = o;
    }
    // warp-aggregated per-graph node counts (batch is sorted -> few groups/warp)
    unsigned m = __match_any_sync(0xffffffffu, bg);
    int lane = threadIdx.x & 31;
    if (bg >= 0 && (int)(__ffs(m) - 1) == lane)
        atomicAdd(&g_cnt[bg], (float)__popc(m));
}

__global__ void __launch_bounds__(256) scatter_kernel(const float* __restrict__ edge_attr,
                                                      const int* __restrict__ esrc,
                                                      const int* __restrict__ edst) {
    int e = blockIdx.x * 256 + threadIdx.x;
    if (e >= N_EDGES) return;
    int d = edst[e];
    int pos = atomicAdd(&g_cursor[d], 1);
    const float4* a = (const float4*)(edge_attr + (size_t)e * 8);
    float4 a0 = __ldg(a), a1 = __ldg(a + 1);
    g_src_s[pos] = esrc[e];
    float4* o = (float4*)(g_ea_s + (size_t)pos * 8);
    o[0] = a0; o[1] = a1;
}

// -------- per-dst aggregation: warp/dst, feature-packed f32x2, 2-edge batch ----
__global__ void __launch_bounds__(256) agg_pass(int cur,
                                                const float* __restrict__ eW,
                                                const float* __restrict__ eb) {
    int lane = threadIdx.x & 31;
    int d = blockIdx.x * 8 + (threadIdx.x >> 5);   // grid 12500 exact
    const float* h = cur ? g_h1 : g_h0;

    // weight slice: lane's 2 adjacent features -> natively packed float2/ull
    ull W0 = __ldg((const ull*)(eW + 0 * 64) + lane);
    ull W1 = __ldg((const ull*)(eW + 1 * 64) + lane);
    ull W2 = __ldg((const ull*)(eW + 2 * 64) + lane);
    ull W3 = __ldg((const ull*)(eW + 3 * 64) + lane);
    ull W4 = __ldg((const ull*)(eW + 4 * 64) + lane);
    ull W5 = __ldg((const ull*)(eW + 5 * 64) + lane);
    ull W6 = __ldg((const ull*)(eW + 6 * 64) + lane);
    ull W7 = __ldg((const ull*)(eW + 7 * 64) + lane);
    ull BB = __ldg((const ull*)eb + lane);
    const ull L2E2 = splat(LOG2E);
    const ull C2   = splat(-SHL2);

    int start = g_off[d];
    int end = start + g_deg[d];
    ull DEN = 0ull, NUM = 0ull;   // packed (feat0, feat1) accumulators (0.0f,0.0f)

#define EBODY(A0, A1, HU) { \
    ull E = fma2_3(splat(A0.x), W0, BB); \
    fma2(E, splat(A0.y), W1); \
    fma2(E, splat(A0.z), W2); \
    fma2(E, splat(A0.w), W3); \
    fma2(E, splat(A1.x), W4); \
    fma2(E, splat(A1.y), W5); \
    fma2(E, splat(A1.z), W6); \
    fma2(E, splat(A1.w), W7); \
    E = add2(E, HU); \
    float t0, t1; unpack2(t0, t1, E); \
    float m0 = fmaxf(t0, 0.0f) + EPSV; \
    float m1 = fmaxf(t1, 0.0f) + EPSV; \
    ull M = pack2(m0, m1); \
    ull ARG = fma2_3(M, L2E2, C2); \
    float a0v, a1v; unpack2(a0v, a1v, ARG); \
    ull X = pack2(exp2f(a0v), exp2f(a1v)); \
    DEN = add2(DEN, X); \
    fma2(NUM, M, X); }

    int i = start;
    for (; i + 2 <= end; i += 2) {
        int s0 = __ldg(g_src_s + i), s1 = __ldg(g_src_s + i + 1);
        const float4* ap = (const float4*)(g_ea_s + (size_t)i * 8);
        float4 a00 = __ldg(ap + 0), a01 = __ldg(ap + 1);
        float4 a10 = __ldg(ap + 2), a11 = __ldg(ap + 3);
        ull H0 = __ldg((const ull*)(h + (size_t)s0 * HDIM) + lane);
        ull H1 = __ldg((const ull*)(h + (size_t)s1 * HDIM) + lane);
        EBODY(a00, a01, H0)
        EBODY(a10, a11, H1)
    }
    if (i < end) {
        int s = __ldg(g_src_s + i);
        const float4* ap = (const float4*)(g_ea_s + (size_t)i * 8);
        float4 a0 = __ldg(ap), a1 = __ldg(ap + 1);
        ull HV = __ldg((const ull*)(h + (size_t)s * HDIM) + lane);
        EBODY(a0, a1, HV)
    }
#undef EBODY

    float den0, den1, num0, num1;
    unpack2(den0, den1, DEN);
    unpack2(num0, num1, NUM);
    float2 out;
    out.x = num0 / fmaxf(den0, 1e-16f);
    out.y = num1 / fmaxf(den1, 1e-16f);
    *(float2*)(g_agg + (size_t)d * HDIM + 2 * lane) = out;
}

// ---------------- node MLP: smem-tiled GEMM, packed f32x2 (+pool on last) ------
#define SX_STRIDE 68
#define SH_STRIDE 68
#define SMEM_FLOATS (8704 + 4352 + 8192)   // 21248 floats = 84992 bytes

__global__ void __launch_bounds__(256, 2) node_mlp(int cur, int last,
                                                   const float* __restrict__ W1,
                                                   const float* __restrict__ b1,
                                                   const float* __restrict__ W2,
                                                   const float* __restrict__ b2,
                                                   const int* __restrict__ batch) {
    extern __shared__ float sm[];
    float* sH  = sm;                 // [128][68]
    float* sX  = sm + 8704;          // [64][68]
    float* sW1 = sm + 8704 + 4352;   // [64][128]
    float* sW2 = sm + 8704;          // [128][64] phase-2 overlay

    int tid = threadIdx.x;
    int base = blockIdx.x * 64;
    const float* h_in  = cur ? g_h1 : g_h0;
    float*       h_out = cur ? g_h0 : g_h1;

    {
        const float4* w4 = (const float4*)W1;
        float4* s4 = (float4*)sW1;
#pragma unroll
        for (int i = 0; i < 8; i++) s4[tid + i * 256] = w4[tid + i * 256];
    }
    for (int idx = tid; idx < 64 * 64; idx += 256) {
        int n = idx >> 6, f = idx & 63;
        int gn = base + n;
        float v = 0.0f;
        if (gn < N_NODES)
            v = h_in[(size_t)gn * HDIM + f] + g_agg[(size_t)gn * HDIM + f];
        sX[f * SX_STRIDE + n] = v;
    }
    __syncthreads();

    int nodeg = tid & 15;   // 4 nodes
    int hidg  = tid >> 4;   // 8 hidden = 4 packed pairs

    ull acc[4][4];
    {
        float4 ba = *(const float4*)&b1[hidg * 8];
        float4 bbv = *(const float4*)&b1[hidg * 8 + 4];
        ull p0 = pack2(ba.x, ba.y), p1 = pack2(ba.z, ba.w);
        ull p2 = pack2(bbv.x, bbv.y), p3 = pack2(bbv.z, bbv.w);
#pragma unroll
        for (int n = 0; n < 4; n++) { acc[n][0] = p0; acc[n][1] = p1; acc[n][2] = p2; acc[n][3] = p3; }
    }
#pragma unroll 4
    for (int k = 0; k < 64; k++) {
        float4 xv = *(const float4*)&sX[k * SX_STRIDE + nodeg * 4];
        ulonglong2 wA = *(const ulonglong2*)&sW1[k * 128 + hidg * 8];
        ulonglong2 wB = *(const ulonglong2*)&sW1[k * 128 + hidg * 8 + 4];
        float xs[4] = { xv.x, xv.y, xv.z, xv.w };
#pragma unroll
        for (int n = 0; n < 4; n++) {
            ull xd = pack2(xs[n], xs[n]);
            fma2(acc[n][0], xd, wA.x);
            fma2(acc[n][1], xd, wA.y);
            fma2(acc[n][2], xd, wB.x);
            fma2(acc[n][3], xd, wB.y);
        }
    }
#pragma unroll
    for (int p = 0; p < 4; p++) {
        float lo[4], hi[4];
#pragma unroll
        for (int n = 0; n < 4; n++) unpack2(lo[n], hi[n], acc[n][p]);
        *(float4*)&sH[(hidg * 8 + 2 * p) * SH_STRIDE + nodeg * 4] =
            make_float4(fmaxf(lo[0], 0.f), fmaxf(lo[1], 0.f), fmaxf(lo[2], 0.f), fmaxf(lo[3], 0.f));
        *(float4*)&sH[(hidg * 8 + 2 * p + 1) * SH_STRIDE + nodeg * 4] =
            make_float4(fmaxf(hi[0], 0.f), fmaxf(hi[1], 0.f), fmaxf(hi[2], 0.f), fmaxf(hi[3], 0.f));
    }
    __syncthreads();

    {
        const float4* w4 = (const float4*)W2;
        float4* s4 = (float4*)sW2;
#pragma unroll
        for (int i = 0; i < 8; i++) s4[tid + i * 256] = w4[tid + i * 256];
    }
    __syncthreads();

    int outg = tid >> 4;
    ull a2[4][2];
    {
        float4 bv = *(const float4*)&b2[outg * 4];
        ull p0 = pack2(bv.x, bv.y), p1 = pack2(bv.z, bv.w);
#pragma unroll
        for (int n = 0; n < 4; n++) { a2[n][0] = p0; a2[n][1] = p1; }
    }
#pragma unroll 4
    for (int k = 0; k < 128; k++) {
        float4 hv = *(const float4*)&sH[k * SH_STRIDE + nodeg * 4];
        ulonglong2 wp = *(const ulonglong2*)&sW2[k * 64 + outg * 4];
        float hs[4] = { hv.x, hv.y, hv.z, hv.w };
#pragma unroll
        for (int n = 0; n < 4; n++) {
            ull xd = pack2(hs[n], hs[n]);
            fma2(a2[n][0], xd, wp.x);
            fma2(a2[n][1], xd, wp.y);
        }
    }
#pragma unroll
    for (int n = 0; n < 4; n++) {
        int gn = base + nodeg * 4 + n;
        if (gn < N_NODES) {
            float r0, r1, r2, r3;
            unpack2(r0, r1, a2[n][0]);
            unpack2(r2, r3, a2[n][1]);
            r0 = fmaxf(r0, 0.f); r1 = fmaxf(r1, 0.f);
            r2 = fmaxf(r2, 0.f); r3 = fmaxf(r3, 0.f);
            if (last) {
                int b = __ldg(batch + gn);
                red4(g_pool + (size_t)b * HDIM + outg * 4, r0, r1, r2, r3);
            } else {
                *(float4*)&h_out[(size_t)gn * HDIM + outg * 4] = make_float4(r0, r1, r2, r3);
            }
        }
    }
}

// ---------------- graph head (also restores g_deg=0 invariant) -----------------
__global__ void __launch_bounds__(256) head_kernel(const float* __restrict__ graph_attr,
                                                   const float* __restrict__ d1W, const float* __restrict__ d1b,
                                                   const float* __restrict__ d2W, const float* __restrict__ d2b,
                                                   const float* __restrict__ oW,  const float* __restrict__ ob,
                                                   float* __restrict__ out) {
    int t = blockIdx.x * 256 + threadIdx.x;
    // restore invariant for the next call (grid = 32768 threads)
    for (int i = t; i < N_NODES; i += (N_GRAPHS * 32)) g_deg[i] = 0;

    int g = t >> 5, lane = t & 31;
    if (g >= N_GRAPHS) return;
    float cnt = fmaxf(g_cnt[g], 1.0f);
    float p0 = g_pool[g * HDIM + lane] / cnt;
    float p1 = g_pool[g * HDIM + 32 + lane] / cnt;
    float ga = (lane < 10) ? graph_attr[g * 10 + lane] : 0.0f;

    float a = d1b[lane];
#pragma unroll
    for (int k = 0; k < 32; k++) a = fmaf(__shfl_sync(0xffffffffu, p0, k), d1W[k * 32 + lane], a);
#pragma unroll
    for (int k = 0; k < 32; k++) a = fmaf(__shfl_sync(0xffffffffu, p1, k), d1W[(32 + k) * 32 + lane], a);
#pragma unroll
    for (int k = 0; k < 10; k++) a = fmaf(__shfl_sync(0xffffffffu, ga, k), d1W[(64 + k) * 32 + lane], a);
    a = fmaxf(a, 0.0f);

    float bsum = d2b[lane];
#pragma unroll
    for (int k = 0; k < 32; k++) bsum = fmaf(__shfl_sync(0xffffffffu, a, k), d2W[k * 32 + lane], bsum);
    bsum = fmaxf(bsum, 0.0f);

    float v = bsum * oW[lane];
#pragma unroll
    for (int s = 16; s > 0; s >>= 1) v += __shfl_xor_sync(0xffffffffu, v, s);
    if (lane == 0) out[g] = 1.0f / (1.0f + expf(-(v + ob[0])));
}

// ---------------- launch -------------------------------------------------------
extern "C" void kernel_launch(void* const* d_in, const int* in_sizes, int n_in,
                              void* d_out, int out_size) {
    const float* x          = (const float*)d_in[0];
    const float* edge_attr  = (const float*)d_in[1];
    const float* graph_attr = (const float*)d_in[2];
    const int*   edge_index = (const int*)d_in[3];
    const int*   batch      = (const int*)d_in[4];
    const float* node_W     = (const float*)d_in[5];
    const float* node_b     = (const float*)d_in[6];
    const float* edge_W     = (const float*)d_in[7];
    const float* edge_b     = (const float*)d_in[8];
    const float* cW1[3] = { (const float*)d_in[9],  (const float*)d_in[13], (const float*)d_in[17] };
    const float* cb1[3] = { (const float*)d_in[10], (const float*)d_in[14], (const float*)d_in[18] };
    const float* cW2[3] = { (const float*)d_in[11], (const float*)d_in[15], (const float*)d_in[19] };
    const float* cb2[3] = { (const float*)d_in[12], (const float*)d_in[16], (const float*)d_in[20] };
    const float* d1W = (const float*)d_in[21];
    const float* d1b = (const float*)d_in[22];
    const float* d2W = (const float*)d_in[23];
    const float* d2b = (const float*)d_in[24];
    const float* oW  = (const float*)d_in[25];
    const float* ob  = (const float*)d_in[26];
    const int* esrc = edge_index;
    const int* edst = edge_index + N_EDGES;
    float* out = (float*)d_out;

    const int SMEM_MLP = SMEM_FLOATS * 4;   // 84992 bytes
    cudaFuncSetAttribute((const void*)node_mlp,
                         cudaFuncAttributeMaxDynamicSharedMemorySize, SMEM_MLP);

    // 1: proj + hist + zeroing (grid exactly covers N_EDGES)
    input_proj<<<N_EDGES / 256, 256>>>(x, node_W, node_b, edst);
    // 2-4: CSR scans + scatter (slot #4 = scatter for ncu)
    scan1_kernel<<<NSCAN, SCAN_BLK>>>();
    scan23_kernel<<<(N_NODES + 255) / 256, 256>>>(batch);
    scatter_kernel<<<(N_EDGES + 255) / 256, 256>>>(edge_attr, esrc, edst);

    int cur = 0;
    const int NBLK_MLP = (N_NODES + 63) / 64;
    for (int c = 0; c < 3; c++) {
        agg_pass<<<N_NODES / 8, 256>>>(cur, edge_W, edge_b);
        node_mlp<<<NBLK_MLP, 256, SMEM_MLP>>>(cur, (c == 2) ? 1 : 0,
                                              cW1[c], cb1[c], cW2[c], cb2[c], batch);
        cur ^= 1;
    }

    head_kernel<<<(N_GRAPHS * 32) / 256, 256>>>(graph_attr, d1W, d1b, d2W, d2b, oW, ob, out);
}